// round 1
// baseline (speedup 1.0000x reference)
#include <cuda_runtime.h>
#include <math.h>

// Problem constants (from reference)
#define B_  4
#define H_  704
#define W_  704
#define HW_ ((long)H_ * (long)W_)   // 495616
#define M_  32
#define P_  128
#define NN_ 129
#define GAIN_ 2.0f

// Stable 2-class logsumexp
__device__ __forceinline__ float lse2(float a, float b) {
    float m = fmaxf(a, b);
    return m + logf(expf(a - m) + expf(b - m));
}

__device__ __forceinline__ float smooth_l1(float d) {
    float a = fabsf(d);
    return (a < 1.0f) ? 0.5f * d * d : a - 0.5f;
}

__global__ void loss_total_kernel(const float* __restrict__ ref_boxes,
                                  const float* __restrict__ pred_class,
                                  const float* __restrict__ pred_regress,
                                  const float* __restrict__ anchor,
                                  const int*   __restrict__ pos_idx,
                                  const int*   __restrict__ neg_idx,
                                  const int*   __restrict__ reg_idx,
                                  float* __restrict__ out) {
    const int b = B_ - 1;  // reference returns losses[-1] only
    const float* rb   = ref_boxes    + (long)b * M_ * 7;
    const float* pc   = pred_class   + (long)b * 4  * HW_;
    const float* pr   = pred_regress + (long)b * 14 * HW_;
    const int*   pidx = pos_idx + b * P_ * 2;
    const int*   nidx = neg_idx + b * NN_ * 2;
    const int*   ridx = reg_idx + b * M_ * 2;   // R = 1

    const int tid = threadIdx.x;
    const int nt  = blockDim.x;

    float pos_sum = 0.0f;   // sum of per-position CE terms (label=1), both channel pairs
    float neg_sum = 0.0f;   // label=0 terms
    float reg_sum = 0.0f;   // sum of smooth-l1 over all (m, 2, 7)

    // ---- positive classification positions ----
    for (int i = tid; i < P_; i += nt) {
        int y = pidx[2 * i];
        int x = pidx[2 * i + 1];
        long off = (long)y * W_ + x;
        float l0 = pc[off];
        float l1 = pc[HW_ + off];
        float l2 = pc[2 * HW_ + off];
        float l3 = pc[3 * HW_ + off];
        // label 1: -(l1 - lse) = lse - l1
        pos_sum += (lse2(l0, l1) - l1) + (lse2(l2, l3) - l3);
    }

    // ---- negative classification positions ----
    for (int i = tid; i < NN_; i += nt) {
        int y = nidx[2 * i];
        int x = nidx[2 * i + 1];
        long off = (long)y * W_ + x;
        float l0 = pc[off];
        float l1 = pc[HW_ + off];
        float l2 = pc[2 * HW_ + off];
        float l3 = pc[3 * HW_ + off];
        // label 0: lse - l0
        neg_sum += (lse2(l0, l1) - l0) + (lse2(l2, l3) - l2);
    }

    // ---- regression boxes (M=32, R=1, 2 anchors x 7 params) ----
    for (int m = tid; m < M_; m += nt) {
        int y = ridx[2 * m];
        int x = ridx[2 * m + 1];
        long off = (long)y * W_ + x;

        float rf[7];
        #pragma unroll
        for (int j = 0; j < 7; j++) rf[j] = rb[m * 7 + j];

        #pragma unroll
        for (int k = 0; k < 2; k++) {
            float a[7];
            #pragma unroll
            for (int j = 0; j < 7; j++)
                a[j] = anchor[((long)(k * 7 + j)) * HW_ + off];

            float diag = sqrtf(a[3] * a[3] + a[4] * a[4]);
            float ov[7];
            ov[0] = (rf[0] - a[0]) / diag;
            ov[1] = (rf[1] - a[1]) / diag;
            ov[2] = (rf[2] - a[2]) / a[5];
            ov[3] = logf(rf[3] / a[3]);
            ov[4] = logf(rf[4] / a[4]);
            ov[5] = logf(rf[5] / a[5]);
            float dth = rf[6] - a[6];
            ov[6] = atan2f(sinf(dth), cosf(dth));

            #pragma unroll
            for (int j = 0; j < 7; j++) {
                float p = pr[((long)(k * 7 + j)) * HW_ + off];
                reg_sum += smooth_l1(p - ov[j]);
            }
        }
    }

    // ---- block reduction (256 threads = 8 warps) ----
    __shared__ float s_pos[8], s_neg[8], s_reg[8];
    const unsigned FULL = 0xFFFFFFFFu;
    #pragma unroll
    for (int o = 16; o > 0; o >>= 1) {
        pos_sum += __shfl_down_sync(FULL, pos_sum, o);
        neg_sum += __shfl_down_sync(FULL, neg_sum, o);
        reg_sum += __shfl_down_sync(FULL, reg_sum, o);
    }
    int warp = tid >> 5, lane = tid & 31;
    if (lane == 0) { s_pos[warp] = pos_sum; s_neg[warp] = neg_sum; s_reg[warp] = reg_sum; }
    __syncthreads();

    if (tid == 0) {
        float ps = 0.0f, ns = 0.0f, rs = 0.0f;
        #pragma unroll
        for (int w = 0; w < 8; w++) { ps += s_pos[w]; ns += s_neg[w]; rs += s_reg[w]; }
        // cls = mean over P (both pairs) + mean over NN (both pairs)
        // reg = (per-box mean over 14 elements) summed over M
        float cls = ps / (float)P_ + ns / (float)NN_;
        float reg = rs / 14.0f;
        out[0] = cls + GAIN_ * reg;
    }
}

extern "C" void kernel_launch(void* const* d_in, const int* in_sizes, int n_in,
                              void* d_out, int out_size) {
    const float* ref_boxes    = (const float*)d_in[0];
    const float* pred_class   = (const float*)d_in[1];
    const float* pred_regress = (const float*)d_in[2];
    const float* anchor       = (const float*)d_in[3];
    const int*   pos_idx      = (const int*)d_in[4];
    const int*   neg_idx      = (const int*)d_in[5];
    const int*   reg_idx      = (const int*)d_in[6];
    float* out = (float*)d_out;

    loss_total_kernel<<<1, 256>>>(ref_boxes, pred_class, pred_regress, anchor,
                                  pos_idx, neg_idx, reg_idx, out);
}

// round 2
// speedup vs baseline: 1.1938x; 1.1938x over previous
#include <cuda_runtime.h>
#include <math.h>

// Problem constants (from reference)
#define B_  4
#define H_  704
#define W_  704
#define HW_ ((long)H_ * (long)W_)   // 495616
#define M_  32
#define P_  128
#define NN_ 129
#define GAIN_ 2.0f
#define TWO_PI_ 6.2831853071795864769f

// softplus(x) = log(1 + exp(x)), stable form. Note lse2(a,b) - b = softplus(a-b).
__device__ __forceinline__ float softplus(float x) {
    // For |x| moderate (logits ~ N(0,1)), fast intrinsics are plenty accurate.
    // Stable: softplus(x) = max(x,0) + log1p(exp(-|x|))
    float ax = fabsf(x);
    float e  = __expf(-ax);
    return fmaxf(x, 0.0f) + __logf(1.0f + e);
}

__device__ __forceinline__ float smooth_l1(float d) {
    float a = fabsf(d);
    return (a < 1.0f) ? 0.5f * d * d : a - 0.5f;
}

__global__ void loss_total_kernel(const float* __restrict__ ref_boxes,
                                  const float* __restrict__ pred_class,
                                  const float* __restrict__ pred_regress,
                                  const float* __restrict__ anchor,
                                  const int*   __restrict__ pos_idx,
                                  const int*   __restrict__ neg_idx,
                                  const int*   __restrict__ reg_idx,
                                  float* __restrict__ out) {
    const int b = B_ - 1;  // reference returns losses[-1] only
    const float* rb   = ref_boxes    + (long)b * M_ * 7;
    const float* pc   = pred_class   + (long)b * 4  * HW_;
    const float* pr   = pred_regress + (long)b * 14 * HW_;
    const int2*  pidx = (const int2*)(pos_idx + b * P_ * 2);
    const int2*  nidx = (const int2*)(neg_idx + b * NN_ * 2);
    const int2*  ridx = (const int2*)(reg_idx + b * M_ * 2);   // R = 1

    const int tid = threadIdx.x;

    float pos_sum = 0.0f;
    float neg_sum = 0.0f;
    float reg_sum = 0.0f;

    // ---- issue all independent index loads up front ----
    // pos: tid < 128 ; neg: tid < 129 (tid 128..255 handle neg idx 128 only on tid==128? no:
    //   neg has 129 entries; threads 0..128 each take one)
    // reg: 64 (m,k) items on threads 0..63
    long poff = -1, noff = -1, roff = -1;
    if (tid < P_) {
        int2 yx = pidx[tid];
        poff = (long)yx.x * W_ + yx.y;
    }
    if (tid < NN_) {
        int2 yx = nidx[tid];
        noff = (long)yx.x * W_ + yx.y;
    }
    int m = tid >> 1, k = tid & 1;
    if (tid < 2 * M_) {
        int2 yx = ridx[m];
        roff = (long)yx.x * W_ + yx.y;
    }

    // ---- gather class logits (independent loads) ----
    float p0, p1, p2, p3, n0, n1, n2, n3;
    if (poff >= 0) {
        p0 = pc[poff];
        p1 = pc[HW_ + poff];
        p2 = pc[2 * HW_ + poff];
        p3 = pc[3 * HW_ + poff];
    }
    if (noff >= 0) {
        n0 = pc[noff];
        n1 = pc[HW_ + noff];
        n2 = pc[2 * HW_ + noff];
        n3 = pc[3 * HW_ + noff];
    }

    // ---- gather anchor + pred_regress for reg items ----
    float a[7], p[7], rf[7];
    if (roff >= 0) {
        #pragma unroll
        for (int j = 0; j < 7; j++)
            a[j] = anchor[((long)(k * 7 + j)) * HW_ + roff];
        #pragma unroll
        for (int j = 0; j < 7; j++)
            p[j] = pr[((long)(k * 7 + j)) * HW_ + roff];
        #pragma unroll
        for (int j = 0; j < 7; j++)
            rf[j] = rb[m * 7 + j];
    }

    // ---- compute ----
    if (poff >= 0) {
        // label 1: lse(l0,l1) - l1 = softplus(l0 - l1)
        pos_sum = softplus(p0 - p1) + softplus(p2 - p3);
    }
    if (noff >= 0) {
        // label 0: lse(l0,l1) - l0 = softplus(l1 - l0)
        neg_sum = softplus(n1 - n0) + softplus(n3 - n2);
    }
    if (roff >= 0) {
        float inv_diag = rsqrtf(a[3] * a[3] + a[4] * a[4]);
        float ov0 = (rf[0] - a[0]) * inv_diag;
        float ov1 = (rf[1] - a[1]) * inv_diag;
        float ov2 = __fdividef(rf[2] - a[2], a[5]);
        float ov3 = __logf(__fdividef(rf[3], a[3]));
        float ov4 = __logf(__fdividef(rf[4], a[4]));
        float ov5 = __logf(__fdividef(rf[5], a[5]));
        float dth = rf[6] - a[6];
        // atan2(sin d, cos d) == wrap d into (-pi, pi]
        float ov6 = dth - TWO_PI_ * rintf(dth * (1.0f / TWO_PI_));

        reg_sum  = smooth_l1(p[0] - ov0);
        reg_sum += smooth_l1(p[1] - ov1);
        reg_sum += smooth_l1(p[2] - ov2);
        reg_sum += smooth_l1(p[3] - ov3);
        reg_sum += smooth_l1(p[4] - ov4);
        reg_sum += smooth_l1(p[5] - ov5);
        reg_sum += smooth_l1(p[6] - ov6);
    }

    // ---- block reduction (256 threads = 8 warps) ----
    __shared__ float s_pos[8], s_neg[8], s_reg[8];
    const unsigned FULL = 0xFFFFFFFFu;
    #pragma unroll
    for (int o = 16; o > 0; o >>= 1) {
        pos_sum += __shfl_down_sync(FULL, pos_sum, o);
        neg_sum += __shfl_down_sync(FULL, neg_sum, o);
        reg_sum += __shfl_down_sync(FULL, reg_sum, o);
    }
    int warp = tid >> 5, lane = tid & 31;
    if (lane == 0) { s_pos[warp] = pos_sum; s_neg[warp] = neg_sum; s_reg[warp] = reg_sum; }
    __syncthreads();

    if (tid == 0) {
        float ps = 0.0f, ns = 0.0f, rs = 0.0f;
        #pragma unroll
        for (int w = 0; w < 8; w++) { ps += s_pos[w]; ns += s_neg[w]; rs += s_reg[w]; }
        float cls = ps / (float)P_ + ns / (float)NN_;
        float reg = rs / 14.0f;
        out[0] = cls + GAIN_ * reg;
    }
}

extern "C" void kernel_launch(void* const* d_in, const int* in_sizes, int n_in,
                              void* d_out, int out_size) {
    const float* ref_boxes    = (const float*)d_in[0];
    const float* pred_class   = (const float*)d_in[1];
    const float* pred_regress = (const float*)d_in[2];
    const float* anchor       = (const float*)d_in[3];
    const int*   pos_idx      = (const int*)d_in[4];
    const int*   neg_idx      = (const int*)d_in[5];
    const int*   reg_idx      = (const int*)d_in[6];
    float* out = (float*)d_out;

    loss_total_kernel<<<1, 256>>>(ref_boxes, pred_class, pred_regress, anchor,
                                  pos_idx, neg_idx, reg_idx, out);
}

// round 3
// speedup vs baseline: 1.3029x; 1.0913x over previous
#include <cuda_runtime.h>
#include <math.h>

// Problem constants (from reference)
#define B_   4
#define H_   704
#define W_   704
#define HW_  ((long)H_ * (long)W_)   // 495616
#define M_   32
#define P_   128
#define NN_  129
#define GAIN_ 2.0f
#define TWO_PI_ 6.2831853071795864769f

// Work decomposition: one item per thread, one warp per block, one block per SM.
// items [0,128)      -> positive classification positions
// items [128,257)    -> negative classification positions (129)
// items [257,321)    -> regression (m,k) pairs, m = i>>1, k = i&1 (64)
#define N_ITEMS   321
#define THREADS_  32
#define N_BLOCKS  ((N_ITEMS + THREADS_ - 1) / THREADS_)   // 11

__device__ float g_partial[N_BLOCKS];
__device__ int   g_ticket = 0;

__device__ __forceinline__ float softplus(float x) {
    float ax = fabsf(x);
    return fmaxf(x, 0.0f) + __logf(1.0f + __expf(-ax));
}

__device__ __forceinline__ float smooth_l1(float d) {
    float a = fabsf(d);
    return (a < 1.0f) ? 0.5f * d * d : a - 0.5f;
}

__global__ void loss_total_kernel(const float* __restrict__ ref_boxes,
                                  const float* __restrict__ pred_class,
                                  const float* __restrict__ pred_regress,
                                  const float* __restrict__ anchor,
                                  const int*   __restrict__ pos_idx,
                                  const int*   __restrict__ neg_idx,
                                  const int*   __restrict__ reg_idx,
                                  float* __restrict__ out) {
    const int b = B_ - 1;  // reference returns losses[-1] only
    const float* rb   = ref_boxes    + (long)b * M_ * 7;
    const float* pc   = pred_class   + (long)b * 4  * HW_;
    const float* pr   = pred_regress + (long)b * 14 * HW_;
    const int2*  pidx = (const int2*)(pos_idx + b * P_ * 2);
    const int2*  nidx = (const int2*)(neg_idx + b * NN_ * 2);
    const int2*  ridx = (const int2*)(reg_idx + b * M_ * 2);   // R = 1

    const int item = blockIdx.x * THREADS_ + threadIdx.x;

    float contrib = 0.0f;

    if (item < P_) {
        // ---- positive classification ----
        int2 yx = __ldg(&pidx[item]);
        long off = (long)yx.x * W_ + yx.y;
        float l0 = pc[off];
        float l1 = pc[HW_ + off];
        float l2 = pc[2 * HW_ + off];
        float l3 = pc[3 * HW_ + off];
        // label 1: lse(l0,l1) - l1 = softplus(l0 - l1)
        contrib = (softplus(l0 - l1) + softplus(l2 - l3)) * (1.0f / (float)P_);
    } else if (item < P_ + NN_) {
        // ---- negative classification ----
        int2 yx = __ldg(&nidx[item - P_]);
        long off = (long)yx.x * W_ + yx.y;
        float l0 = pc[off];
        float l1 = pc[HW_ + off];
        float l2 = pc[2 * HW_ + off];
        float l3 = pc[3 * HW_ + off];
        // label 0: lse(l0,l1) - l0 = softplus(l1 - l0)
        contrib = (softplus(l1 - l0) + softplus(l3 - l2)) * (1.0f / (float)NN_);
    } else if (item < N_ITEMS) {
        // ---- regression (m, k) ----
        int i = item - (P_ + NN_);
        int m = i >> 1, k = i & 1;
        int2 yx = __ldg(&ridx[m]);
        long off = (long)yx.x * W_ + yx.y;

        float a[7], p[7], rf[7];
        #pragma unroll
        for (int j = 0; j < 7; j++)
            a[j] = anchor[((long)(k * 7 + j)) * HW_ + off];
        #pragma unroll
        for (int j = 0; j < 7; j++)
            p[j] = pr[((long)(k * 7 + j)) * HW_ + off];
        #pragma unroll
        for (int j = 0; j < 7; j++)
            rf[j] = __ldg(&rb[m * 7 + j]);

        float inv_diag = rsqrtf(a[3] * a[3] + a[4] * a[4]);
        float ov0 = (rf[0] - a[0]) * inv_diag;
        float ov1 = (rf[1] - a[1]) * inv_diag;
        float ov2 = __fdividef(rf[2] - a[2], a[5]);
        float ov3 = __logf(__fdividef(rf[3], a[3]));
        float ov4 = __logf(__fdividef(rf[4], a[4]));
        float ov5 = __logf(__fdividef(rf[5], a[5]));
        float dth = rf[6] - a[6];
        // atan2(sin d, cos d) == wrap d into (-pi, pi]
        float ov6 = dth - TWO_PI_ * rintf(dth * (1.0f / TWO_PI_));

        float s  = smooth_l1(p[0] - ov0);
        s += smooth_l1(p[1] - ov1);
        s += smooth_l1(p[2] - ov2);
        s += smooth_l1(p[3] - ov3);
        s += smooth_l1(p[4] - ov4);
        s += smooth_l1(p[5] - ov5);
        s += smooth_l1(p[6] - ov6);
        contrib = s * (GAIN_ / 14.0f);
    }

    // ---- warp reduction (single warp per block) ----
    const unsigned FULL = 0xFFFFFFFFu;
    #pragma unroll
    for (int o = 16; o > 0; o >>= 1)
        contrib += __shfl_down_sync(FULL, contrib, o);

    if (threadIdx.x == 0) {
        g_partial[blockIdx.x] = contrib;
        __threadfence();
        int ticket = atomicAdd(&g_ticket, 1);
        if (ticket == N_BLOCKS - 1) {
            // last block finalizes
            float total = 0.0f;
            #pragma unroll
            for (int w = 0; w < N_BLOCKS; w++)
                total += g_partial[w];
            out[0] = total;
            g_ticket = 0;   // reset for next (graph-replayed) launch
        }
    }
}

extern "C" void kernel_launch(void* const* d_in, const int* in_sizes, int n_in,
                              void* d_out, int out_size) {
    const float* ref_boxes    = (const float*)d_in[0];
    const float* pred_class   = (const float*)d_in[1];
    const float* pred_regress = (const float*)d_in[2];
    const float* anchor       = (const float*)d_in[3];
    const int*   pos_idx      = (const int*)d_in[4];
    const int*   neg_idx      = (const int*)d_in[5];
    const int*   reg_idx      = (const int*)d_in[6];
    float* out = (float*)d_out;

    loss_total_kernel<<<N_BLOCKS, THREADS_>>>(ref_boxes, pred_class, pred_regress,
                                              anchor, pos_idx, neg_idx, reg_idx, out);
}